// round 4
// baseline (speedup 1.0000x reference)
#include <cuda_runtime.h>
#include <cstdint>

#define NP_PEP  50000
#define NP_PROT 8000
#define NE      1600000
#define NEL     200000
#define FIN     1280
#define H       128

// ---------------- scratch (static device globals; no runtime allocation) ----
__device__ float g_hp0[NP_PEP * H];
__device__ float g_hp1[NP_PEP * H];
__device__ float g_mp [NP_PEP * H];
__device__ float g_hr0[NP_PROT * H];
__device__ float g_hr1[NP_PROT * H];
__device__ float g_mr [NP_PROT * H];

__device__ int g_cnt_prot[NP_PROT];
__device__ int g_cnt_pep [NP_PEP];
__device__ int g_rp_prot [NP_PROT + 1];
__device__ int g_rp_pep  [NP_PEP + 1];
__device__ int g_cur_prot[NP_PROT];
__device__ int g_cur_pep [NP_PEP];
__device__ int g_adj_prot[NE];   // src pep ids grouped by prot dst
__device__ int g_adj_pep [NE];   // dst prot ids grouped by pep src

// ---------------- small helper kernels --------------------------------------
__global__ void zero2_kernel(int* a, int na, int* b, int nb) {
    int stride = gridDim.x * blockDim.x;
    for (int i = blockIdx.x * blockDim.x + threadIdx.x; i < na; i += stride) a[i] = 0;
    for (int i = blockIdx.x * blockDim.x + threadIdx.x; i < nb; i += stride) b[i] = 0;
}

__global__ void hist_kernel(const int* __restrict__ e_src, const int* __restrict__ e_dst,
                            int* __restrict__ cnt_prot, int* __restrict__ cnt_pep, int n) {
    int stride = gridDim.x * blockDim.x;
    for (int i = blockIdx.x * blockDim.x + threadIdx.x; i < n; i += stride) {
        atomicAdd(&cnt_prot[e_dst[i]], 1);
        atomicAdd(&cnt_pep [e_src[i]], 1);
    }
}

// single-block exclusive scan: rp[0..n] and cursor copy
__global__ void scan_kernel(const int* __restrict__ cnt, int* __restrict__ rp,
                            int* __restrict__ cur, int n) {
    __shared__ int sums[1024];
    int tid = threadIdx.x;
    int chunk = (n + 1023) >> 10;
    int s = tid * chunk;
    int e = s + chunk; if (e > n) e = n; if (s > n) s = n;
    int loc = 0;
    for (int i = s; i < e; ++i) loc += cnt[i];
    sums[tid] = loc;
    __syncthreads();
    for (int off = 1; off < 1024; off <<= 1) {
        int v = (tid >= off) ? sums[tid - off] : 0;
        __syncthreads();
        sums[tid] += v;
        __syncthreads();
    }
    int run = sums[tid] - loc;  // exclusive prefix for this chunk
    for (int i = s; i < e; ++i) {
        rp[i] = run; cur[i] = run;
        run += cnt[i];
    }
    if (tid == 1023) rp[n] = sums[1023];
}

__global__ void scatter_kernel(const int* __restrict__ e_src, const int* __restrict__ e_dst,
                               int* __restrict__ cur_prot, int* __restrict__ cur_pep,
                               int* __restrict__ adj_prot, int* __restrict__ adj_pep, int n) {
    int stride = gridDim.x * blockDim.x;
    for (int i = blockIdx.x * blockDim.x + threadIdx.x; i < n; i += stride) {
        int s = e_src[i], d = e_dst[i];
        int p = atomicAdd(&cur_prot[d], 1);
        adj_prot[p] = s;
        int q = atomicAdd(&cur_pep[s], 1);
        adj_pep[q] = d;
    }
}

// ---------------- CSR mean aggregation: one block per destination node ------
__global__ void __launch_bounds__(128) agg_mean_kernel(
    const float* __restrict__ hsrc, const int* __restrict__ rp,
    const int* __restrict__ adj, float* __restrict__ m, int n_dst) {
    int d = blockIdx.x;
    if (d >= n_dst) return;
    int s0 = rp[d], s1 = rp[d + 1];
    int lane = threadIdx.x & 31;
    int w    = threadIdx.x >> 5;

    float4 acc = make_float4(0.f, 0.f, 0.f, 0.f);
    for (int e = s0 + w; e < s1; e += 4) {
        int src = __ldg(&adj[e]);
        float4 v = ((const float4*)(hsrc + (size_t)src * H))[lane];
        acc.x += v.x; acc.y += v.y; acc.z += v.z; acc.w += v.w;
    }
    __shared__ float4 red[4][32];
    red[w][lane] = acc;
    __syncthreads();
    if (w == 0) {
        float4 a = red[0][lane], b = red[1][lane], c = red[2][lane], dd = red[3][lane];
        float deg = (float)(s1 - s0);
        float inv = deg > 0.f ? 1.f / deg : 0.f;
        float4 o;
        o.x = (a.x + b.x + c.x + dd.x) * inv;
        o.y = (a.y + b.y + c.y + dd.y) * inv;
        o.z = (a.z + b.z + c.z + dd.z) * inv;
        o.w = (a.w + b.w + c.w + dd.w) * inv;
        ((float4*)(m + (size_t)d * H))[lane] = o;
    }
}

// ---------------- dual SGEMM: C[M,128] = relu?(A1@W1 + A2@W2 + bias) --------
// BM=64, BN=128 (=H), BK=16, 128 threads, 8x8 per thread
#define BM 64
#define BN 128
#define BK 16

__global__ void __launch_bounds__(128) gemm_dual_kernel(
    const float* __restrict__ A1, const float* __restrict__ W1, int K1,
    const float* __restrict__ A2, const float* __restrict__ W2, int K2,
    const float* __restrict__ bias, float* __restrict__ C, int M, int do_relu) {

    __shared__ float As[BK][BM + 4];
    __shared__ float Bs[BK][BN];

    int tid  = threadIdx.x;
    int tcol = tid & 15;   // 16 col-groups of 8
    int trow = tid >> 4;   // 8 row-groups of 8
    int m0   = blockIdx.x * BM;

    float acc[8][8];
#pragma unroll
    for (int i = 0; i < 8; ++i)
#pragma unroll
        for (int j = 0; j < 8; ++j) acc[i][j] = 0.f;

    for (int seg = 0; seg < 2; ++seg) {
        const float* A = seg ? A2 : A1;
        const float* W = seg ? W2 : W1;
        int K = seg ? K2 : K1;
        if (K == 0 || A == nullptr) continue;
        int nkb = K / BK;
        for (int kb = 0; kb < nkb; ++kb) {
            // load A tile (64x16) transposed into As[k][row]
#pragma unroll
            for (int l = 0; l < 2; ++l) {
                int f = tid + l * 128;      // 0..255 float4 slots
                int row = f >> 2, c4 = f & 3;
                float4 v = make_float4(0.f, 0.f, 0.f, 0.f);
                int gr = m0 + row;
                if (gr < M) v = *(const float4*)(A + (size_t)gr * K + kb * BK + c4 * 4);
                As[c4 * 4 + 0][row] = v.x;
                As[c4 * 4 + 1][row] = v.y;
                As[c4 * 4 + 2][row] = v.z;
                As[c4 * 4 + 3][row] = v.w;
            }
            // load W tile (16x128)
#pragma unroll
            for (int l = 0; l < 4; ++l) {
                int f = tid + l * 128;      // 0..511 float4 slots
                int r = f >> 5, c = f & 31;
                float4 v = *(const float4*)(W + (size_t)(kb * BK + r) * BN + c * 4);
                *(float4*)&Bs[r][c * 4] = v;
            }
            __syncthreads();
#pragma unroll
            for (int k = 0; k < BK; ++k) {
                float a[8], b[8];
                *(float4*)&a[0] = *(const float4*)&As[k][trow * 8];
                *(float4*)&a[4] = *(const float4*)&As[k][trow * 8 + 4];
                *(float4*)&b[0] = *(const float4*)&Bs[k][tcol * 8];
                *(float4*)&b[4] = *(const float4*)&Bs[k][tcol * 8 + 4];
#pragma unroll
                for (int i = 0; i < 8; ++i)
#pragma unroll
                    for (int j = 0; j < 8; ++j)
                        acc[i][j] += a[i] * b[j];
            }
            __syncthreads();
        }
    }

    float bj[8];
#pragma unroll
    for (int j = 0; j < 8; ++j) bj[j] = bias[tcol * 8 + j];

#pragma unroll
    for (int i = 0; i < 8; ++i) {
        int gr = m0 + trow * 8 + i;
        if (gr >= M) continue;
#pragma unroll
        for (int j = 0; j < 8; j += 4) {
            float4 v;
            v.x = acc[i][j + 0] + bj[j + 0];
            v.y = acc[i][j + 1] + bj[j + 1];
            v.z = acc[i][j + 2] + bj[j + 2];
            v.w = acc[i][j + 3] + bj[j + 3];
            if (do_relu) {
                v.x = fmaxf(v.x, 0.f); v.y = fmaxf(v.y, 0.f);
                v.z = fmaxf(v.z, 0.f); v.w = fmaxf(v.w, 0.f);
            }
            *(float4*)(C + (size_t)gr * BN + tcol * 8 + j) = v;
        }
    }
}

// ---------------- classifier: warp per edge, 128-dim dot --------------------
__global__ void classifier_kernel(const float* __restrict__ hp, const float* __restrict__ hr,
                                  const int* __restrict__ es, const int* __restrict__ ed,
                                  float* __restrict__ out, int n) {
    int gtid = blockIdx.x * blockDim.x + threadIdx.x;
    int wid  = gtid >> 5;
    int lane = threadIdx.x & 31;
    int nw   = (gridDim.x * blockDim.x) >> 5;
    for (int e = wid; e < n; e += nw) {
        int s = es[e], d = ed[e];
        float4 a = ((const float4*)(hp + (size_t)s * H))[lane];
        float4 b = ((const float4*)(hr + (size_t)d * H))[lane];
        float v = a.x * b.x + a.y * b.y + a.z * b.z + a.w * b.w;
#pragma unroll
        for (int o = 16; o; o >>= 1) v += __shfl_xor_sync(0xFFFFFFFFu, v, o);
        if (lane == 0) out[e] = v;
    }
}

// ---------------- launch ------------------------------------------------------
extern "C" void kernel_launch(void* const* d_in, const int* in_sizes, int n_in,
                              void* d_out, int out_size) {
    const float* x_pep  = (const float*)d_in[0];
    const float* x_prot = (const float*)d_in[1];
    const int*   e_src  = (const int*)d_in[2];
    const int*   e_dst  = (const int*)d_in[3];
    const int*   el_src = (const int*)d_in[4];
    const int*   el_dst = (const int*)d_in[5];

    // metadata order detection: reference-arg order has b1_bind (128 elems) at
    // index 12; setup_inputs() dict order has Wl1_rev (16384) there.
    bool ref_order = (in_sizes[12] == H);
    const float *W_pep, *b_pep, *W_prot, *b_prot;
    const float *Wl1b, *Wr1b, *b1b, *Wl1r, *Wr1r, *b1r;
    const float *Wl2b, *Wr2b, *b2b, *Wl2r, *Wr2r, *b2r;
    W_pep  = (const float*)d_in[6];
    b_pep  = (const float*)d_in[7];
    W_prot = (const float*)d_in[8];
    b_prot = (const float*)d_in[9];
    if (ref_order) {
        Wl1b = (const float*)d_in[10]; Wr1b = (const float*)d_in[11]; b1b = (const float*)d_in[12];
        Wl1r = (const float*)d_in[13]; Wr1r = (const float*)d_in[14]; b1r = (const float*)d_in[15];
        Wl2b = (const float*)d_in[16]; Wr2b = (const float*)d_in[17]; b2b = (const float*)d_in[18];
        Wl2r = (const float*)d_in[19]; Wr2r = (const float*)d_in[20]; b2r = (const float*)d_in[21];
    } else {
        Wl1b = (const float*)d_in[10]; Wr1b = (const float*)d_in[11];
        Wl1r = (const float*)d_in[12]; Wr1r = (const float*)d_in[13];
        Wl2b = (const float*)d_in[14]; Wr2b = (const float*)d_in[15];
        Wl2r = (const float*)d_in[16]; Wr2r = (const float*)d_in[17];
        b1b  = (const float*)d_in[18]; b1r  = (const float*)d_in[19];
        b2b  = (const float*)d_in[20]; b2r  = (const float*)d_in[21];
    }
    float* out = (float*)d_out;

    // resolve scratch symbol addresses
    float *hp0, *hp1, *mp, *hr0, *hr1, *mr;
    int *cnt_p, *cnt_q, *rp_p, *rp_q, *cur_p, *cur_q, *adj_p, *adj_q;
    cudaGetSymbolAddress((void**)&hp0, g_hp0);
    cudaGetSymbolAddress((void**)&hp1, g_hp1);
    cudaGetSymbolAddress((void**)&mp,  g_mp);
    cudaGetSymbolAddress((void**)&hr0, g_hr0);
    cudaGetSymbolAddress((void**)&hr1, g_hr1);
    cudaGetSymbolAddress((void**)&mr,  g_mr);
    cudaGetSymbolAddress((void**)&cnt_p, g_cnt_prot);
    cudaGetSymbolAddress((void**)&cnt_q, g_cnt_pep);
    cudaGetSymbolAddress((void**)&rp_p,  g_rp_prot);
    cudaGetSymbolAddress((void**)&rp_q,  g_rp_pep);
    cudaGetSymbolAddress((void**)&cur_p, g_cur_prot);
    cudaGetSymbolAddress((void**)&cur_q, g_cur_pep);
    cudaGetSymbolAddress((void**)&adj_p, g_adj_prot);
    cudaGetSymbolAddress((void**)&adj_q, g_adj_pep);

    // ---- CSR build ----
    zero2_kernel<<<256, 256>>>(cnt_p, NP_PROT, cnt_q, NP_PEP);
    hist_kernel<<<2048, 256>>>(e_src, e_dst, cnt_p, cnt_q, NE);
    scan_kernel<<<1, 1024>>>(cnt_p, rp_p, cur_p, NP_PROT);
    scan_kernel<<<1, 1024>>>(cnt_q, rp_q, cur_q, NP_PEP);
    scatter_kernel<<<2048, 256>>>(e_src, e_dst, cur_p, cur_q, adj_p, adj_q, NE);

    // ---- input projections ----
    gemm_dual_kernel<<<(NP_PEP + BM - 1) / BM, 128>>>(
        x_pep, W_pep, FIN, nullptr, nullptr, 0, b_pep, hp0, NP_PEP, 0);
    gemm_dual_kernel<<<(NP_PROT + BM - 1) / BM, 128>>>(
        x_prot, W_prot, FIN, nullptr, nullptr, 0, b_prot, hr0, NP_PROT, 0);

    // ---- SAGE layer 1 (+ relu) ----
    agg_mean_kernel<<<NP_PROT, 128>>>(hp0, rp_p, adj_p, mr, NP_PROT);
    gemm_dual_kernel<<<(NP_PROT + BM - 1) / BM, 128>>>(
        mr, Wl1b, H, hr0, Wr1b, H, b1b, hr1, NP_PROT, 1);
    agg_mean_kernel<<<NP_PEP, 128>>>(hr0, rp_q, adj_q, mp, NP_PEP);
    gemm_dual_kernel<<<(NP_PEP + BM - 1) / BM, 128>>>(
        mp, Wl1r, H, hp0, Wr1r, H, b1r, hp1, NP_PEP, 1);

    // ---- SAGE layer 2 (no relu) ----
    agg_mean_kernel<<<NP_PROT, 128>>>(hp1, rp_p, adj_p, mr, NP_PROT);
    gemm_dual_kernel<<<(NP_PROT + BM - 1) / BM, 128>>>(
        mr, Wl2b, H, hr1, Wr2b, H, b2b, hr0, NP_PROT, 0);
    agg_mean_kernel<<<NP_PEP, 128>>>(hr1, rp_q, adj_q, mp, NP_PEP);
    gemm_dual_kernel<<<(NP_PEP + BM - 1) / BM, 128>>>(
        mp, Wl2r, H, hp1, Wr2r, H, b2r, hp0, NP_PEP, 0);

    // ---- classifier ----
    classifier_kernel<<<1024, 256>>>(hp0, hr0, el_src, el_dst, out, NEL);
}

// round 6
// speedup vs baseline: 1.0755x; 1.0755x over previous
#include <cuda_runtime.h>
#include <cuda_bf16.h>
#include <cstdint>

#define NP_PEP  50000
#define NP_PROT 8000
#define NE      1600000
#define NEL     200000
#define FIN     1280
#define H       128

// ---------------- scratch (static device globals; no runtime allocation) ----
__device__ float g_hp0[NP_PEP * H];
__device__ float g_hp1[NP_PEP * H];
__device__ float g_mp [NP_PEP * H];
__device__ float g_hr0[NP_PROT * H];
__device__ float g_hr1[NP_PROT * H];
__device__ float g_mr [NP_PROT * H];

__device__ int g_cnt_prot[NP_PROT];
__device__ int g_cnt_pep [NP_PEP];
__device__ int g_rp_prot [NP_PROT + 1];
__device__ int g_rp_pep  [NP_PEP + 1];
__device__ int g_cur_prot[NP_PROT];
__device__ int g_cur_pep [NP_PEP];
__device__ int g_part_prot[64];
__device__ int g_part_pep [64];
__device__ int g_adj_prot[NE];   // src pep ids grouped by prot dst
__device__ int g_adj_pep [NE];   // dst prot ids grouped by pep src

// ---------------- small helper kernels --------------------------------------
__global__ void zero2_kernel(int* a, int na, int* b, int nb) {
    int stride = gridDim.x * blockDim.x;
    for (int i = blockIdx.x * blockDim.x + threadIdx.x; i < na; i += stride) a[i] = 0;
    for (int i = blockIdx.x * blockDim.x + threadIdx.x; i < nb; i += stride) b[i] = 0;
}

__global__ void hist_kernel(const int* __restrict__ e_src, const int* __restrict__ e_dst,
                            int* __restrict__ cnt_prot, int* __restrict__ cnt_pep, int n) {
    int stride = gridDim.x * blockDim.x;
    for (int i = blockIdx.x * blockDim.x + threadIdx.x; i < n; i += stride) {
        atomicAdd(&cnt_prot[e_dst[i]], 1);
        atomicAdd(&cnt_pep [e_src[i]], 1);
    }
}

// ---------------- hierarchical scan: reduce / scan-partials / write ---------
#define SNB 64
#define SNT 256

__global__ void scan_reduce_kernel(const int* __restrict__ cnt, int* __restrict__ part, int n) {
    __shared__ int sh[SNT];
    int b = blockIdx.x, t = threadIdx.x;
    int chunk = (n + SNB - 1) / SNB;
    int s = b * chunk;
    int e = s + chunk; if (e > n) e = n;
    int loc = 0;
    for (int i = s + t; i < e; i += SNT) loc += cnt[i];
    sh[t] = loc;
    __syncthreads();
    for (int off = SNT / 2; off; off >>= 1) {
        if (t < off) sh[t] += sh[t + off];
        __syncthreads();
    }
    if (t == 0) part[b] = sh[0];
}

__global__ void scan_partial_kernel(int* __restrict__ part, int* __restrict__ rp, int n) {
    __shared__ int sh[SNB];
    int t = threadIdx.x;
    int v = part[t];
    sh[t] = v;
    __syncthreads();
    for (int off = 1; off < SNB; off <<= 1) {
        int u = (t >= off) ? sh[t - off] : 0;
        __syncthreads();
        sh[t] += u;
        __syncthreads();
    }
    part[t] = sh[t] - v;           // exclusive prefix of block partials
    if (t == SNB - 1) rp[n] = sh[t];
}

__global__ void scan_write_kernel(const int* __restrict__ cnt, const int* __restrict__ part,
                                  int* __restrict__ rp, int* __restrict__ cur, int n) {
    __shared__ int sh[SNT];
    __shared__ int base;
    int b = blockIdx.x, t = threadIdx.x;
    int chunk = (n + SNB - 1) / SNB;
    int s = b * chunk;
    int e = s + chunk; if (e > n) e = n;
    if (t == 0) base = part[b];
    int per = (chunk + SNT - 1) / SNT;
    int ts = s + t * per;
    int te = ts + per; if (te > e) te = e; if (ts > e) ts = e;
    int loc = 0;
    for (int i = ts; i < te; ++i) loc += cnt[i];
    sh[t] = loc;
    __syncthreads();
    int v = loc;
    for (int off = 1; off < SNT; off <<= 1) {
        int u = (t >= off) ? sh[t - off] : 0;
        __syncthreads();
        sh[t] += u;
        __syncthreads();
    }
    int run = base + sh[t] - v;    // exclusive prefix for this thread's range
    for (int i = ts; i < te; ++i) {
        rp[i] = run; cur[i] = run;
        run += cnt[i];
    }
}

__global__ void scatter_kernel(const int* __restrict__ e_src, const int* __restrict__ e_dst,
                               int* __restrict__ cur_prot, int* __restrict__ cur_pep,
                               int* __restrict__ adj_prot, int* __restrict__ adj_pep, int n) {
    int stride = gridDim.x * blockDim.x;
    for (int i = blockIdx.x * blockDim.x + threadIdx.x; i < n; i += stride) {
        int s = e_src[i], d = e_dst[i];
        int p = atomicAdd(&cur_prot[d], 1);
        adj_prot[p] = s;
        int q = atomicAdd(&cur_pep[s], 1);
        adj_pep[q] = d;
    }
}

// ---------------- CSR mean aggregation: one block per destination node ------
__global__ void __launch_bounds__(128) agg_mean_kernel(
    const float* __restrict__ hsrc, const int* __restrict__ rp,
    const int* __restrict__ adj, float* __restrict__ m, int n_dst) {
    int d = blockIdx.x;
    if (d >= n_dst) return;
    int s0 = rp[d], s1 = rp[d + 1];
    int lane = threadIdx.x & 31;
    int w    = threadIdx.x >> 5;

    float4 acc = make_float4(0.f, 0.f, 0.f, 0.f);
    for (int e = s0 + w; e < s1; e += 4) {
        int src = __ldg(&adj[e]);
        float4 v = ((const float4*)(hsrc + (size_t)src * H))[lane];
        acc.x += v.x; acc.y += v.y; acc.z += v.z; acc.w += v.w;
    }
    __shared__ float4 red[4][32];
    red[w][lane] = acc;
    __syncthreads();
    if (w == 0) {
        float4 a = red[0][lane], b = red[1][lane], c = red[2][lane], dd = red[3][lane];
        float deg = (float)(s1 - s0);
        float inv = deg > 0.f ? 1.f / deg : 0.f;
        float4 o;
        o.x = (a.x + b.x + c.x + dd.x) * inv;
        o.y = (a.y + b.y + c.y + dd.y) * inv;
        o.z = (a.z + b.z + c.z + dd.z) * inv;
        o.w = (a.w + b.w + c.w + dd.w) * inv;
        ((float4*)(m + (size_t)d * H))[lane] = o;
    }
}

// ---------------- bf16-split (3x) tensor-core GEMM --------------------------
// C[M,128] = relu?(A1@W1 + A2@W2 + bias), fp32 in/out, mma.sync bf16 inside.
// BM=128, BN=128(=H), BK=32, 256 threads = 8 warps (2x4 warp grid, 64x32 each)
#define GBM 128
#define GBK 32
#define SLD 40    // smem row stride in bf16 elems (80B = 5x16B -> ldmatrix conflict-free)

__device__ __forceinline__ void mma_bf16(float* c,
    uint32_t a0, uint32_t a1, uint32_t a2, uint32_t a3, uint32_t b0, uint32_t b1) {
    asm volatile(
        "mma.sync.aligned.m16n8k16.row.col.f32.bf16.bf16.f32 "
        "{%0,%1,%2,%3}, {%4,%5,%6,%7}, {%8,%9}, {%0,%1,%2,%3};"
        : "+f"(c[0]), "+f"(c[1]), "+f"(c[2]), "+f"(c[3])
        : "r"(a0), "r"(a1), "r"(a2), "r"(a3), "r"(b0), "r"(b1));
}

__device__ __forceinline__ void ldsm4(uint32_t* r, uint32_t addr) {
    asm volatile("ldmatrix.sync.aligned.m8n8.x4.shared.b16 {%0,%1,%2,%3}, [%4];"
        : "=r"(r[0]), "=r"(r[1]), "=r"(r[2]), "=r"(r[3]) : "r"(addr));
}

__global__ void __launch_bounds__(256) gemm_bf16x3_kernel(
    const float* __restrict__ A1, const float* __restrict__ W1, int K1,
    const float* __restrict__ A2, const float* __restrict__ W2, int K2,
    const float* __restrict__ bias, float* __restrict__ C, int M, int do_relu) {

    __shared__ __align__(16) __nv_bfloat16 As_hi[GBM * SLD];
    __shared__ __align__(16) __nv_bfloat16 As_lo[GBM * SLD];
    __shared__ __align__(16) __nv_bfloat16 Bs_hi[H * SLD];
    __shared__ __align__(16) __nv_bfloat16 Bs_lo[H * SLD];

    int tid  = threadIdx.x;
    int lane = tid & 31, wid = tid >> 5;
    int wm = wid & 1;        // 0..1 : 64-row half
    int wn = wid >> 1;       // 0..3 : 32-col group
    int m0 = blockIdx.x * GBM;

    float c[4][4][4];
#pragma unroll
    for (int i = 0; i < 4; ++i)
#pragma unroll
        for (int j = 0; j < 4; ++j)
#pragma unroll
            for (int k = 0; k < 4; ++k) c[i][j][k] = 0.f;

    int s1 = K1 / GBK;
    int s2 = (A2 != nullptr) ? (K2 / GBK) : 0;
    int ns = s1 + s2;

    // global->reg prefetch state
    float4 rA[4], rB[4];
    int arow = tid >> 1;                 // 0..127
    int kq   = (tid & 1) * 16;           // 0 or 16
    bool avalid = (m0 + arow) < M;

    auto LOAD = [&](int s) {
        const float* A; const float* W; int K; int kb;
        if (s < s1) { A = A1; W = W1; K = K1; kb = s; }
        else        { A = A2; W = W2; K = K2; kb = s - s1; }
        const float* ap = A + (size_t)(m0 + arow) * K + kb * GBK + kq;
#pragma unroll
        for (int j = 0; j < 4; ++j)
            rA[j] = avalid ? *(const float4*)(ap + j * 4) : make_float4(0.f, 0.f, 0.f, 0.f);
#pragma unroll
        for (int l = 0; l < 4; ++l) {
            int f = tid + l * 256;
            int kr = f >> 5, c4 = (f & 31) * 4;
            rB[l] = *(const float4*)(W + (size_t)(kb * GBK + kr) * H + c4);
        }
    };

    auto STORE = [&]() {
#pragma unroll
        for (int j = 0; j < 4; ++j) {
            float x[4] = { rA[j].x, rA[j].y, rA[j].z, rA[j].w };
            __nv_bfloat16 h[4], l[4];
#pragma unroll
            for (int q = 0; q < 4; ++q) {
                h[q] = __float2bfloat16(x[q]);
                l[q] = __float2bfloat16(x[q] - __bfloat162float(h[q]));
            }
            int base = arow * SLD + kq + j * 4;
            __nv_bfloat162 p;
            p.x = h[0]; p.y = h[1]; *(__nv_bfloat162*)&As_hi[base]     = p;
            p.x = h[2]; p.y = h[3]; *(__nv_bfloat162*)&As_hi[base + 2] = p;
            p.x = l[0]; p.y = l[1]; *(__nv_bfloat162*)&As_lo[base]     = p;
            p.x = l[2]; p.y = l[3]; *(__nv_bfloat162*)&As_lo[base + 2] = p;
        }
#pragma unroll
        for (int ll = 0; ll < 4; ++ll) {
            int f = tid + ll * 256;
            int kr = f >> 5, c4 = (f & 31) * 4;
            float x[4] = { rB[ll].x, rB[ll].y, rB[ll].z, rB[ll].w };
#pragma unroll
            for (int j = 0; j < 4; ++j) {
                __nv_bfloat16 hh = __float2bfloat16(x[j]);
                Bs_hi[(c4 + j) * SLD + kr] = hh;
                Bs_lo[(c4 + j) * SLD + kr] = __float2bfloat16(x[j] - __bfloat162float(hh));
            }
        }
    };

    // per-lane ldmatrix row/col offsets
    int a_r = (lane & 7) + ((lane >> 3) & 1) * 8;
    int a_c = (lane >> 4) * 8;
    int b_r = (lane & 7) + ((lane >> 4) & 1) * 8;
    int b_c = ((lane >> 3) & 1) * 8;
    uint32_t as_hi = (uint32_t)__cvta_generic_to_shared(As_hi);
    uint32_t as_lo = (uint32_t)__cvta_generic_to_shared(As_lo);
    uint32_t bs_hi = (uint32_t)__cvta_generic_to_shared(Bs_hi);
    uint32_t bs_lo = (uint32_t)__cvta_generic_to_shared(Bs_lo);

    auto COMPUTE = [&]() {
#pragma unroll
        for (int kk = 0; kk < GBK; kk += 16) {
            uint32_t ah[4][4], al[4][4], bh[2][4], bl[2][4];
#pragma unroll
            for (int mt = 0; mt < 4; ++mt) {
                uint32_t off = (uint32_t)(((wm * 64 + mt * 16 + a_r) * SLD + kk + a_c) * 2);
                ldsm4(ah[mt], as_hi + off);
                ldsm4(al[mt], as_lo + off);
            }
#pragma unroll
            for (int p = 0; p < 2; ++p) {
                uint32_t off = (uint32_t)(((wn * 32 + p * 16 + b_r) * SLD + kk + b_c) * 2);
                ldsm4(bh[p], bs_hi + off);
                ldsm4(bl[p], bs_lo + off);
            }
#pragma unroll
            for (int mt = 0; mt < 4; ++mt)
#pragma unroll
                for (int nt = 0; nt < 4; ++nt) {
                    uint32_t h0 = bh[nt >> 1][(nt & 1) * 2], h1 = bh[nt >> 1][(nt & 1) * 2 + 1];
                    uint32_t l0 = bl[nt >> 1][(nt & 1) * 2], l1 = bl[nt >> 1][(nt & 1) * 2 + 1];
                    mma_bf16(c[mt][nt], ah[mt][0], ah[mt][1], ah[mt][2], ah[mt][3], h0, h1);
                    mma_bf16(c[mt][nt], ah[mt][0], ah[mt][1], ah[mt][2], ah[mt][3], l0, l1);
                    mma_bf16(c[mt][nt], al[mt][0], al[mt][1], al[mt][2], al[mt][3], h0, h1);
                }
        }
    };

    LOAD(0);
    for (int s = 0; s < ns; ++s) {
        __syncthreads();           // previous compute done before smem overwrite
        STORE();
        __syncthreads();
        if (s + 1 < ns) LOAD(s + 1);   // LDGs overlap with mma below
        COMPUTE();
    }

    // epilogue: bias (+relu) and fp32 store
    int g = lane >> 2, t = lane & 3;
#pragma unroll
    for (int mt = 0; mt < 4; ++mt) {
        int r0 = m0 + wm * 64 + mt * 16 + g;
#pragma unroll
        for (int nt = 0; nt < 4; ++nt) {
            int col = wn * 32 + nt * 8 + t * 2;
            float2 bv = *(const float2*)&bias[col];
            float o0 = c[mt][nt][0] + bv.x, o1 = c[mt][nt][1] + bv.y;
            float o2 = c[mt][nt][2] + bv.x, o3 = c[mt][nt][3] + bv.y;
            if (do_relu) {
                o0 = fmaxf(o0, 0.f); o1 = fmaxf(o1, 0.f);
                o2 = fmaxf(o2, 0.f); o3 = fmaxf(o3, 0.f);
            }
            if (r0 < M) { float2 v = make_float2(o0, o1); *(float2*)&C[(size_t)r0 * H + col] = v; }
            int r1 = r0 + 8;
            if (r1 < M) { float2 v = make_float2(o2, o3); *(float2*)&C[(size_t)r1 * H + col] = v; }
        }
    }
}

// ---------------- classifier: warp per edge, 128-dim dot --------------------
__global__ void classifier_kernel(const float* __restrict__ hp, const float* __restrict__ hr,
                                  const int* __restrict__ es, const int* __restrict__ ed,
                                  float* __restrict__ out, int n) {
    int gtid = blockIdx.x * blockDim.x + threadIdx.x;
    int wid  = gtid >> 5;
    int lane = threadIdx.x & 31;
    int nw   = (gridDim.x * blockDim.x) >> 5;
    for (int e = wid; e < n; e += nw) {
        int s = es[e], d = ed[e];
        float4 a = ((const float4*)(hp + (size_t)s * H))[lane];
        float4 b = ((const float4*)(hr + (size_t)d * H))[lane];
        float v = a.x * b.x + a.y * b.y + a.z * b.z + a.w * b.w;
#pragma unroll
        for (int o = 16; o; o >>= 1) v += __shfl_xor_sync(0xFFFFFFFFu, v, o);
        if (lane == 0) out[e] = v;
    }
}

// ---------------- launch ------------------------------------------------------
extern "C" void kernel_launch(void* const* d_in, const int* in_sizes, int n_in,
                              void* d_out, int out_size) {
    const float* x_pep  = (const float*)d_in[0];
    const float* x_prot = (const float*)d_in[1];
    const int*   e_src  = (const int*)d_in[2];
    const int*   e_dst  = (const int*)d_in[3];
    const int*   el_src = (const int*)d_in[4];
    const int*   el_dst = (const int*)d_in[5];

    bool ref_order = (in_sizes[12] == H);
    const float *W_pep  = (const float*)d_in[6];
    const float *b_pep  = (const float*)d_in[7];
    const float *W_prot = (const float*)d_in[8];
    const float *b_prot = (const float*)d_in[9];
    const float *Wl1b, *Wr1b, *b1b, *Wl1r, *Wr1r, *b1r;
    const float *Wl2b, *Wr2b, *b2b, *Wl2r, *Wr2r, *b2r;
    if (ref_order) {
        Wl1b = (const float*)d_in[10]; Wr1b = (const float*)d_in[11]; b1b = (const float*)d_in[12];
        Wl1r = (const float*)d_in[13]; Wr1r = (const float*)d_in[14]; b1r = (const float*)d_in[15];
        Wl2b = (const float*)d_in[16]; Wr2b = (const float*)d_in[17]; b2b = (const float*)d_in[18];
        Wl2r = (const float*)d_in[19]; Wr2r = (const float*)d_in[20]; b2r = (const float*)d_in[21];
    } else {
        Wl1b = (const float*)d_in[10]; Wr1b = (const float*)d_in[11];
        Wl1r = (const float*)d_in[12]; Wr1r = (const float*)d_in[13];
        Wl2b = (const float*)d_in[14]; Wr2b = (const float*)d_in[15];
        Wl2r = (const float*)d_in[16]; Wr2r = (const float*)d_in[17];
        b1b  = (const float*)d_in[18]; b1r  = (const float*)d_in[19];
        b2b  = (const float*)d_in[20]; b2r  = (const float*)d_in[21];
    }
    float* out = (float*)d_out;

    float *hp0, *hp1, *mp, *hr0, *hr1, *mr;
    int *cnt_p, *cnt_q, *rp_p, *rp_q, *cur_p, *cur_q, *adj_p, *adj_q, *part_p, *part_q;
    cudaGetSymbolAddress((void**)&hp0, g_hp0);
    cudaGetSymbolAddress((void**)&hp1, g_hp1);
    cudaGetSymbolAddress((void**)&mp,  g_mp);
    cudaGetSymbolAddress((void**)&hr0, g_hr0);
    cudaGetSymbolAddress((void**)&hr1, g_hr1);
    cudaGetSymbolAddress((void**)&mr,  g_mr);
    cudaGetSymbolAddress((void**)&cnt_p,  g_cnt_prot);
    cudaGetSymbolAddress((void**)&cnt_q,  g_cnt_pep);
    cudaGetSymbolAddress((void**)&rp_p,   g_rp_prot);
    cudaGetSymbolAddress((void**)&rp_q,   g_rp_pep);
    cudaGetSymbolAddress((void**)&cur_p,  g_cur_prot);
    cudaGetSymbolAddress((void**)&cur_q,  g_cur_pep);
    cudaGetSymbolAddress((void**)&adj_p,  g_adj_prot);
    cudaGetSymbolAddress((void**)&adj_q,  g_adj_pep);
    cudaGetSymbolAddress((void**)&part_p, g_part_prot);
    cudaGetSymbolAddress((void**)&part_q, g_part_pep);

    // ---- CSR build ----
    zero2_kernel<<<256, 256>>>(cnt_p, NP_PROT, cnt_q, NP_PEP);
    hist_kernel<<<2048, 256>>>(e_src, e_dst, cnt_p, cnt_q, NE);
    scan_reduce_kernel<<<SNB, SNT>>>(cnt_p, part_p, NP_PROT);
    scan_reduce_kernel<<<SNB, SNT>>>(cnt_q, part_q, NP_PEP);
    scan_partial_kernel<<<1, SNB>>>(part_p, rp_p, NP_PROT);
    scan_partial_kernel<<<1, SNB>>>(part_q, rp_q, NP_PEP);
    scan_write_kernel<<<SNB, SNT>>>(cnt_p, part_p, rp_p, cur_p, NP_PROT);
    scan_write_kernel<<<SNB, SNT>>>(cnt_q, part_q, rp_q, cur_q, NP_PEP);
    scatter_kernel<<<2048, 256>>>(e_src, e_dst, cur_p, cur_q, adj_p, adj_q, NE);

    int gb_pep  = (NP_PEP  + GBM - 1) / GBM;   // 391
    int gb_prot = (NP_PROT + GBM - 1) / GBM;   // 63

    // ---- input projections ----
    gemm_bf16x3_kernel<<<gb_pep, 256>>>(
        x_pep, W_pep, FIN, nullptr, nullptr, 0, b_pep, hp0, NP_PEP, 0);
    gemm_bf16x3_kernel<<<gb_prot, 256>>>(
        x_prot, W_prot, FIN, nullptr, nullptr, 0, b_prot, hr0, NP_PROT, 0);

    // ---- SAGE layer 1 (+ relu) ----
    agg_mean_kernel<<<NP_PROT, 128>>>(hp0, rp_p, adj_p, mr, NP_PROT);
    gemm_bf16x3_kernel<<<gb_prot, 256>>>(
        mr, Wl1b, H, hr0, Wr1b, H, b1b, hr1, NP_PROT, 1);
    agg_mean_kernel<<<NP_PEP, 128>>>(hr0, rp_q, adj_q, mp, NP_PEP);
    gemm_bf16x3_kernel<<<gb_pep, 256>>>(
        mp, Wl1r, H, hp0, Wr1r, H, b1r, hp1, NP_PEP, 1);

    // ---- SAGE layer 2 (no relu) ----
    agg_mean_kernel<<<NP_PROT, 128>>>(hp1, rp_p, adj_p, mr, NP_PROT);
    gemm_bf16x3_kernel<<<gb_prot, 256>>>(
        mr, Wl2b, H, hr1, Wr2b, H, b2b, hr0, NP_PROT, 0);
    agg_mean_kernel<<<NP_PEP, 128>>>(hr1, rp_q, adj_q, mp, NP_PEP);
    gemm_bf16x3_kernel<<<gb_pep, 256>>>(
        mp, Wl2r, H, hp1, Wr2r, H, b2r, hp0, NP_PEP, 0);

    // ---- classifier ----
    classifier_kernel<<<1024, 256>>>(hp0, hr0, el_src, el_dst, out, NEL);
}

// round 9
// speedup vs baseline: 1.4526x; 1.3507x over previous
#include <cuda_runtime.h>
#include <cuda_bf16.h>
#include <cstdint>

#define NP_PEP  50000
#define NP_PROT 8000
#define NE      1600000
#define NEL     200000
#define FIN     1280
#define H       128

// ---------------- scratch (static device globals; no runtime allocation) ----
__device__ float g_hp0[NP_PEP * H];
__device__ float g_hp1[NP_PEP * H];
__device__ float g_mp [NP_PEP * H];
__device__ float g_hr0[NP_PROT * H];
__device__ float g_hr1[NP_PROT * H];
__device__ float g_mr [NP_PROT * H];

__device__ int g_cnt_prot[NP_PROT];
__device__ int g_cnt_pep [NP_PEP];
__device__ int g_rp_prot [NP_PROT + 1];
__device__ int g_rp_pep  [NP_PEP + 1];
__device__ int g_cur_prot[NP_PROT];
__device__ int g_cur_pep [NP_PEP];
__device__ int g_part_prot[64];
__device__ int g_part_pep [64];
__device__ int g_adj_prot[NE];   // src pep ids grouped by prot dst
__device__ int g_adj_pep [NE];   // dst prot ids grouped by pep src

// ---------------- small helper kernels --------------------------------------
__global__ void zero2_kernel(int* a, int na, int* b, int nb) {
    int stride = gridDim.x * blockDim.x;
    for (int i = blockIdx.x * blockDim.x + threadIdx.x; i < na; i += stride) a[i] = 0;
    for (int i = blockIdx.x * blockDim.x + threadIdx.x; i < nb; i += stride) b[i] = 0;
}

__global__ void hist_kernel(const int* __restrict__ e_src, const int* __restrict__ e_dst,
                            int* __restrict__ cnt_prot, int* __restrict__ cnt_pep, int n) {
    int stride = gridDim.x * blockDim.x;
    for (int i = blockIdx.x * blockDim.x + threadIdx.x; i < n; i += stride) {
        atomicAdd(&cnt_prot[e_dst[i]], 1);
        atomicAdd(&cnt_pep [e_src[i]], 1);
    }
}

// ---------------- hierarchical scan: reduce / scan-partials / write ---------
#define SNB 64
#define SNT 256

__global__ void scan_reduce_kernel(const int* __restrict__ cnt, int* __restrict__ part, int n) {
    __shared__ int sh[SNT];
    int b = blockIdx.x, t = threadIdx.x;
    int chunk = (n + SNB - 1) / SNB;
    int s = b * chunk;
    int e = s + chunk; if (e > n) e = n;
    int loc = 0;
    for (int i = s + t; i < e; i += SNT) loc += cnt[i];
    sh[t] = loc;
    __syncthreads();
    for (int off = SNT / 2; off; off >>= 1) {
        if (t < off) sh[t] += sh[t + off];
        __syncthreads();
    }
    if (t == 0) part[b] = sh[0];
}

__global__ void scan_partial_kernel(int* __restrict__ part, int* __restrict__ rp, int n) {
    __shared__ int sh[SNB];
    int t = threadIdx.x;
    int v = part[t];
    sh[t] = v;
    __syncthreads();
    for (int off = 1; off < SNB; off <<= 1) {
        int u = (t >= off) ? sh[t - off] : 0;
        __syncthreads();
        sh[t] += u;
        __syncthreads();
    }
    part[t] = sh[t] - v;           // exclusive prefix of block partials
    if (t == SNB - 1) rp[n] = sh[t];
}

__global__ void scan_write_kernel(const int* __restrict__ cnt, const int* __restrict__ part,
                                  int* __restrict__ rp, int* __restrict__ cur, int n) {
    __shared__ int sh[SNT];
    __shared__ int base;
    int b = blockIdx.x, t = threadIdx.x;
    int chunk = (n + SNB - 1) / SNB;
    int s = b * chunk;
    int e = s + chunk; if (e > n) e = n;
    if (t == 0) base = part[b];
    int per = (chunk + SNT - 1) / SNT;
    int ts = s + t * per;
    int te = ts + per; if (te > e) te = e; if (ts > e) ts = e;
    int loc = 0;
    for (int i = ts; i < te; ++i) loc += cnt[i];
    sh[t] = loc;
    __syncthreads();
    int v = loc;
    for (int off = 1; off < SNT; off <<= 1) {
        int u = (t >= off) ? sh[t - off] : 0;
        __syncthreads();
        sh[t] += u;
        __syncthreads();
    }
    int run = base + sh[t] - v;    // exclusive prefix for this thread's range
    for (int i = ts; i < te; ++i) {
        rp[i] = run; cur[i] = run;
        run += cnt[i];
    }
}

__global__ void scatter_kernel(const int* __restrict__ e_src, const int* __restrict__ e_dst,
                               int* __restrict__ cur_prot, int* __restrict__ cur_pep,
                               int* __restrict__ adj_prot, int* __restrict__ adj_pep, int n) {
    int stride = gridDim.x * blockDim.x;
    for (int i = blockIdx.x * blockDim.x + threadIdx.x; i < n; i += stride) {
        int s = e_src[i], d = e_dst[i];
        int p = atomicAdd(&cur_prot[d], 1);
        adj_prot[p] = s;
        int q = atomicAdd(&cur_pep[s], 1);
        adj_pep[q] = d;
    }
}

// ---------------- CSR mean aggregation: one block per destination node ------
__global__ void __launch_bounds__(128) agg_mean_kernel(
    const float* __restrict__ hsrc, const int* __restrict__ rp,
    const int* __restrict__ adj, float* __restrict__ m, int n_dst) {
    int d = blockIdx.x;
    if (d >= n_dst) return;
    int s0 = rp[d], s1 = rp[d + 1];
    int lane = threadIdx.x & 31;
    int w    = threadIdx.x >> 5;

    float4 acc = make_float4(0.f, 0.f, 0.f, 0.f);
    for (int e = s0 + w; e < s1; e += 4) {
        int src = __ldg(&adj[e]);
        float4 v = ((const float4*)(hsrc + (size_t)src * H))[lane];
        acc.x += v.x; acc.y += v.y; acc.z += v.z; acc.w += v.w;
    }
    __shared__ float4 red[4][32];
    red[w][lane] = acc;
    __syncthreads();
    if (w == 0) {
        float4 a = red[0][lane], b = red[1][lane], c = red[2][lane], dd = red[3][lane];
        float deg = (float)(s1 - s0);
        float inv = deg > 0.f ? 1.f / deg : 0.f;
        float4 o;
        o.x = (a.x + b.x + c.x + dd.x) * inv;
        o.y = (a.y + b.y + c.y + dd.y) * inv;
        o.z = (a.z + b.z + c.z + dd.z) * inv;
        o.w = (a.w + b.w + c.w + dd.w) * inv;
        ((float4*)(m + (size_t)d * H))[lane] = o;
    }
}

// ---------------- bf16-split (3x) tensor-core GEMM --------------------------
// C[M,128] = relu?(A1@W1 + A2@W2 + bias), fp32 in/out, mma.sync bf16 inside.
// BM=128, BN=128(=H), BK=32, 256 threads = 8 warps (2x4 warp grid, 64x32 each)
#define GBM 128
#define GBK 32
#define SLD 40    // smem row stride in bf16 elems (80B = 5x16B -> ldmatrix conflict-free)

__device__ __forceinline__ void mma_bf16(float* c,
    uint32_t a0, uint32_t a1, uint32_t a2, uint32_t a3, uint32_t b0, uint32_t b1) {
    asm volatile(
        "mma.sync.aligned.m16n8k16.row.col.f32.bf16.bf16.f32 "
        "{%0,%1,%2,%3}, {%4,%5,%6,%7}, {%8,%9}, {%0,%1,%2,%3};"
        : "+f"(c[0]), "+f"(c[1]), "+f"(c[2]), "+f"(c[3])
        : "r"(a0), "r"(a1), "r"(a2), "r"(a3), "r"(b0), "r"(b1));
}

__device__ __forceinline__ void ldsm4(uint32_t* r, uint32_t addr) {
    asm volatile("ldmatrix.sync.aligned.m8n8.x4.shared.b16 {%0,%1,%2,%3}, [%4];"
        : "=r"(r[0]), "=r"(r[1]), "=r"(r[2]), "=r"(r[3]) : "r"(addr));
}

__global__ void __launch_bounds__(256) gemm_bf16x3_kernel(
    const float* __restrict__ A1, const float* __restrict__ W1, int K1,
    const float* __restrict__ A2, const float* __restrict__ W2, int K2,
    const float* __restrict__ bias, float* __restrict__ C, int M, int do_relu) {

    __shared__ __align__(16) __nv_bfloat16 As_hi[GBM * SLD];
    __shared__ __align__(16) __nv_bfloat16 As_lo[GBM * SLD];
    __shared__ __align__(16) __nv_bfloat16 Bs_hi[H * SLD];
    __shared__ __align__(16) __nv_bfloat16 Bs_lo[H * SLD];

    int tid  = threadIdx.x;
    int lane = tid & 31, wid = tid >> 5;
    int wm = wid & 1;        // 0..1 : 64-row half
    int wn = wid >> 1;       // 0..3 : 32-col group
    int m0 = blockIdx.x * GBM;

    float c[4][4][4];
#pragma unroll
    for (int i = 0; i < 4; ++i)
#pragma unroll
        for (int j = 0; j < 4; ++j)
#pragma unroll
            for (int k = 0; k < 4; ++k) c[i][j][k] = 0.f;

    int s1 = K1 / GBK;
    int s2 = (A2 != nullptr) ? (K2 / GBK) : 0;
    int ns = s1 + s2;

    // global->reg prefetch state
    float4 rA[4], rB[4];
    int arow = tid >> 1;                 // 0..127
    int kq   = (tid & 1) * 16;           // 0 or 16
    bool avalid = (m0 + arow) < M;

    auto LOAD = [&](int s) {
        const float* A; const float* W; int K; int kb;
        if (s < s1) { A = A1; W = W1; K = K1; kb = s; }
        else        { A = A2; W = W2; K = K2; kb = s - s1; }
        const float* ap = A + (size_t)(m0 + arow) * K + kb * GBK + kq;
#pragma unroll
        for (int j = 0; j < 4; ++j)
            rA[j] = avalid ? *(const float4*)(ap + j * 4) : make_float4(0.f, 0.f, 0.f, 0.f);
#pragma unroll
        for (int l = 0; l < 4; ++l) {
            int f = tid + l * 256;
            int kr = f >> 5, c4 = (f & 31) * 4;
            rB[l] = *(const float4*)(W + (size_t)(kb * GBK + kr) * H + c4);
        }
    };

    auto STORE = [&]() {
#pragma unroll
        for (int j = 0; j < 4; ++j) {
            float x[4] = { rA[j].x, rA[j].y, rA[j].z, rA[j].w };
            __nv_bfloat16 h[4], l[4];
#pragma unroll
            for (int q = 0; q < 4; ++q) {
                h[q] = __float2bfloat16(x[q]);
                l[q] = __float2bfloat16(x[q] - __bfloat162float(h[q]));
            }
            int base = arow * SLD + kq + j * 4;
            __nv_bfloat162 p;
            p.x = h[0]; p.y = h[1]; *(__nv_bfloat162*)&As_hi[base]     = p;
            p.x = h[2]; p.y = h[3]; *(__nv_bfloat162*)&As_hi[base + 2] = p;
            p.x = l[0]; p.y = l[1]; *(__nv_bfloat162*)&As_lo[base]     = p;
            p.x = l[2]; p.y = l[3]; *(__nv_bfloat162*)&As_lo[base + 2] = p;
        }
#pragma unroll
        for (int ll = 0; ll < 4; ++ll) {
            int f = tid + ll * 256;
            int kr = f >> 5, c4 = (f & 31) * 4;
            float x[4] = { rB[ll].x, rB[ll].y, rB[ll].z, rB[ll].w };
#pragma unroll
            for (int j = 0; j < 4; ++j) {
                __nv_bfloat16 hh = __float2bfloat16(x[j]);
                Bs_hi[(c4 + j) * SLD + kr] = hh;
                Bs_lo[(c4 + j) * SLD + kr] = __float2bfloat16(x[j] - __bfloat162float(hh));
            }
        }
    };

    // per-lane ldmatrix row/col offsets
    int a_r = (lane & 7) + ((lane >> 3) & 1) * 8;
    int a_c = (lane >> 4) * 8;
    int b_r = (lane & 7) + ((lane >> 4) & 1) * 8;
    int b_c = ((lane >> 3) & 1) * 8;
    uint32_t as_hi = (uint32_t)__cvta_generic_to_shared(As_hi);
    uint32_t as_lo = (uint32_t)__cvta_generic_to_shared(As_lo);
    uint32_t bs_hi = (uint32_t)__cvta_generic_to_shared(Bs_hi);
    uint32_t bs_lo = (uint32_t)__cvta_generic_to_shared(Bs_lo);

    auto COMPUTE = [&]() {
#pragma unroll
        for (int kk = 0; kk < GBK; kk += 16) {
            uint32_t ah[4][4], al[4][4], bh[2][4], bl[2][4];
#pragma unroll
            for (int mt = 0; mt < 4; ++mt) {
                uint32_t off = (uint32_t)(((wm * 64 + mt * 16 + a_r) * SLD + kk + a_c) * 2);
                ldsm4(ah[mt], as_hi + off);
                ldsm4(al[mt], as_lo + off);
            }
#pragma unroll
            for (int p = 0; p < 2; ++p) {
                uint32_t off = (uint32_t)(((wn * 32 + p * 16 + b_r) * SLD + kk + b_c) * 2);
                ldsm4(bh[p], bs_hi + off);
                ldsm4(bl[p], bs_lo + off);
            }
#pragma unroll
            for (int mt = 0; mt < 4; ++mt)
#pragma unroll
                for (int nt = 0; nt < 4; ++nt) {
                    uint32_t h0 = bh[nt >> 1][(nt & 1) * 2], h1 = bh[nt >> 1][(nt & 1) * 2 + 1];
                    uint32_t l0 = bl[nt >> 1][(nt & 1) * 2], l1 = bl[nt >> 1][(nt & 1) * 2 + 1];
                    mma_bf16(c[mt][nt], ah[mt][0], ah[mt][1], ah[mt][2], ah[mt][3], h0, h1);
                    mma_bf16(c[mt][nt], ah[mt][0], ah[mt][1], ah[mt][2], ah[mt][3], l0, l1);
                    mma_bf16(c[mt][nt], al[mt][0], al[mt][1], al[mt][2], al[mt][3], h0, h1);
                }
        }
    };

    LOAD(0);
    for (int s = 0; s < ns; ++s) {
        __syncthreads();           // previous compute done before smem overwrite
        STORE();
        __syncthreads();
        if (s + 1 < ns) LOAD(s + 1);   // LDGs overlap with mma below
        COMPUTE();
    }

    // epilogue: bias (+relu) and fp32 store
    int g = lane >> 2, t = lane & 3;
#pragma unroll
    for (int mt = 0; mt < 4; ++mt) {
        int r0 = m0 + wm * 64 + mt * 16 + g;
#pragma unroll
        for (int nt = 0; nt < 4; ++nt) {
            int col = wn * 32 + nt * 8 + t * 2;
            float2 bv = *(const float2*)&bias[col];
            float o0 = c[mt][nt][0] + bv.x, o1 = c[mt][nt][1] + bv.y;
            float o2 = c[mt][nt][2] + bv.x, o3 = c[mt][nt][3] + bv.y;
            if (do_relu) {
                o0 = fmaxf(o0, 0.f); o1 = fmaxf(o1, 0.f);
                o2 = fmaxf(o2, 0.f); o3 = fmaxf(o3, 0.f);
            }
            if (r0 < M) { float2 v = make_float2(o0, o1); *(float2*)&C[(size_t)r0 * H + col] = v; }
            int r1 = r0 + 8;
            if (r1 < M) { float2 v = make_float2(o2, o3); *(float2*)&C[(size_t)r1 * H + col] = v; }
        }
    }
}

// ---------------- classifier: warp per edge, 128-dim dot --------------------
__global__ void classifier_kernel(const float* __restrict__ hp, const float* __restrict__ hr,
                                  const int* __restrict__ es, const int* __restrict__ ed,
                                  float* __restrict__ out, int n) {
    int gtid = blockIdx.x * blockDim.x + threadIdx.x;
    int wid  = gtid >> 5;
    int lane = threadIdx.x & 31;
    int nw   = (gridDim.x * blockDim.x) >> 5;
    for (int e = wid; e < n; e += nw) {
        int s = es[e], d = ed[e];
        float4 a = ((const float4*)(hp + (size_t)s * H))[lane];
        float4 b = ((const float4*)(hr + (size_t)d * H))[lane];
        float v = a.x * b.x + a.y * b.y + a.z * b.z + a.w * b.w;
#pragma unroll
        for (int o = 16; o; o >>= 1) v += __shfl_xor_sync(0xFFFFFFFFu, v, o);
        if (lane == 0) out[e] = v;
    }
}

// ---------------- launch ------------------------------------------------------
extern "C" void kernel_launch(void* const* d_in, const int* in_sizes, int n_in,
                              void* d_out, int out_size) {
    const float* x_pep  = (const float*)d_in[0];
    const float* x_prot = (const float*)d_in[1];
    const int*   e_src  = (const int*)d_in[2];
    const int*   e_dst  = (const int*)d_in[3];
    const int*   el_src = (const int*)d_in[4];
    const int*   el_dst = (const int*)d_in[5];

    bool ref_order = (in_sizes[12] == H);
    const float *W_pep  = (const float*)d_in[6];
    const float *b_pep  = (const float*)d_in[7];
    const float *W_prot = (const float*)d_in[8];
    const float *b_prot = (const float*)d_in[9];
    const float *Wl1b, *Wr1b, *b1b, *Wl1r, *Wr1r, *b1r;
    const float *Wl2b, *Wr2b, *b2b, *Wl2r, *Wr2r, *b2r;
    if (ref_order) {
        Wl1b = (const float*)d_in[10]; Wr1b = (const float*)d_in[11]; b1b = (const float*)d_in[12];
        Wl1r = (const float*)d_in[13]; Wr1r = (const float*)d_in[14]; b1r = (const float*)d_in[15];
        Wl2b = (const float*)d_in[16]; Wr2b = (const float*)d_in[17]; b2b = (const float*)d_in[18];
        Wl2r = (const float*)d_in[19]; Wr2r = (const float*)d_in[20]; b2r = (const float*)d_in[21];
    } else {
        Wl1b = (const float*)d_in[10]; Wr1b = (const float*)d_in[11];
        Wl1r = (const float*)d_in[12]; Wr1r = (const float*)d_in[13];
        Wl2b = (const float*)d_in[14]; Wr2b = (const float*)d_in[15];
        Wl2r = (const float*)d_in[16]; Wr2r = (const float*)d_in[17];
        b1b  = (const float*)d_in[18]; b1r  = (const float*)d_in[19];
        b2b  = (const float*)d_in[20]; b2r  = (const float*)d_in[21];
    }
    float* out = (float*)d_out;

    float *hp0, *hp1, *mp, *hr0, *hr1, *mr;
    int *cnt_p, *cnt_q, *rp_p, *rp_q, *cur_p, *cur_q, *adj_p, *adj_q, *part_p, *part_q;
    cudaGetSymbolAddress((void**)&hp0, g_hp0);
    cudaGetSymbolAddress((void**)&hp1, g_hp1);
    cudaGetSymbolAddress((void**)&mp,  g_mp);
    cudaGetSymbolAddress((void**)&hr0, g_hr0);
    cudaGetSymbolAddress((void**)&hr1, g_hr1);
    cudaGetSymbolAddress((void**)&mr,  g_mr);
    cudaGetSymbolAddress((void**)&cnt_p,  g_cnt_prot);
    cudaGetSymbolAddress((void**)&cnt_q,  g_cnt_pep);
    cudaGetSymbolAddress((void**)&rp_p,   g_rp_prot);
    cudaGetSymbolAddress((void**)&rp_q,   g_rp_pep);
    cudaGetSymbolAddress((void**)&cur_p,  g_cur_prot);
    cudaGetSymbolAddress((void**)&cur_q,  g_cur_pep);
    cudaGetSymbolAddress((void**)&adj_p,  g_adj_prot);
    cudaGetSymbolAddress((void**)&adj_q,  g_adj_pep);
    cudaGetSymbolAddress((void**)&part_p, g_part_prot);
    cudaGetSymbolAddress((void**)&part_q, g_part_pep);

    // ---- streams/events for graph-level concurrency (host objects only; ----
    // ---- created once, no device memory involved)                        ----
    static cudaStream_t sA = nullptr, sB = nullptr;
    static cudaEvent_t  evF0 = nullptr, evF1 = nullptr, evF2 = nullptr;
    static cudaEvent_t  evA0 = nullptr, evB0 = nullptr, evA1 = nullptr, evB1 = nullptr;
    static cudaEvent_t  evA2 = nullptr, evB2 = nullptr;
    if (sA == nullptr) {
        cudaStreamCreateWithFlags(&sA, cudaStreamNonBlocking);
        cudaStreamCreateWithFlags(&sB, cudaStreamNonBlocking);
        cudaEventCreateWithFlags(&evF0, cudaEventDisableTiming);
        cudaEventCreateWithFlags(&evF1, cudaEventDisableTiming);
        cudaEventCreateWithFlags(&evF2, cudaEventDisableTiming);
        cudaEventCreateWithFlags(&evA0, cudaEventDisableTiming);
        cudaEventCreateWithFlags(&evB0, cudaEventDisableTiming);
        cudaEventCreateWithFlags(&evA1, cudaEventDisableTiming);
        cudaEventCreateWithFlags(&evB1, cudaEventDisableTiming);
        cudaEventCreateWithFlags(&evA2, cudaEventDisableTiming);
        cudaEventCreateWithFlags(&evB2, cudaEventDisableTiming);
    }
    // s0 must be the stream the harness captures; <<<>>> maps to the default
    // stream, which previous rounds proved is the captured one.
    cudaStream_t s0 = cudaStreamPerThread;
    // If the legacy stream is the capturing one, fall back to it.
    {
        cudaStreamCaptureStatus st = cudaStreamCaptureStatusNone;
        cudaStreamIsCapturing(cudaStreamPerThread, &st);
        if (st != cudaStreamCaptureStatusActive) {
            cudaStreamCaptureStatus st2 = cudaStreamCaptureStatusNone;
            cudaStreamIsCapturing(cudaStreamLegacy, &st2);
            if (st2 == cudaStreamCaptureStatusActive) s0 = cudaStreamLegacy;
        }
    }

    int gb_pep  = (NP_PEP  + GBM - 1) / GBM;   // 391
    int gb_prot = (NP_PROT + GBM - 1) / GBM;   // 63

    // ==== PHASE 0: fork — CSR build (s0) ∥ pep proj (sA) ∥ prot proj (sB) ====
    cudaEventRecord(evF0, s0);
    cudaStreamWaitEvent(sA, evF0, 0);
    cudaStreamWaitEvent(sB, evF0, 0);

    gemm_bf16x3_kernel<<<gb_pep, 256, 0, sA>>>(
        x_pep, W_pep, FIN, nullptr, nullptr, 0, b_pep, hp0, NP_PEP, 0);
    gemm_bf16x3_kernel<<<gb_prot, 256, 0, sB>>>(
        x_prot, W_prot, FIN, nullptr, nullptr, 0, b_prot, hr0, NP_PROT, 0);

    zero2_kernel<<<256, 256, 0, s0>>>(cnt_p, NP_PROT, cnt_q, NP_PEP);
    hist_kernel<<<2048, 256, 0, s0>>>(e_src, e_dst, cnt_p, cnt_q, NE);
    scan_reduce_kernel<<<SNB, SNT, 0, s0>>>(cnt_p, part_p, NP_PROT);
    scan_reduce_kernel<<<SNB, SNT, 0, s0>>>(cnt_q, part_q, NP_PEP);
    scan_partial_kernel<<<1, SNB, 0, s0>>>(part_p, rp_p, NP_PROT);
    scan_partial_kernel<<<1, SNB, 0, s0>>>(part_q, rp_q, NP_PEP);
    scan_write_kernel<<<SNB, SNT, 0, s0>>>(cnt_p, part_p, rp_p, cur_p, NP_PROT);
    scan_write_kernel<<<SNB, SNT, 0, s0>>>(cnt_q, part_q, rp_q, cur_q, NP_PEP);
    scatter_kernel<<<2048, 256, 0, s0>>>(e_src, e_dst, cur_p, cur_q, adj_p, adj_q, NE);

    // join all three
    cudaEventRecord(evA0, sA);
    cudaEventRecord(evB0, sB);
    cudaStreamWaitEvent(s0, evA0, 0);
    cudaStreamWaitEvent(s0, evB0, 0);

    // ==== PHASE 1: SAGE layer 1 — prot chain (sA) ∥ pep chain (sB) ====
    cudaEventRecord(evF1, s0);
    cudaStreamWaitEvent(sA, evF1, 0);
    cudaStreamWaitEvent(sB, evF1, 0);

    agg_mean_kernel<<<NP_PROT, 128, 0, sA>>>(hp0, rp_p, adj_p, mr, NP_PROT);
    gemm_bf16x3_kernel<<<gb_prot, 256, 0, sA>>>(
        mr, Wl1b, H, hr0, Wr1b, H, b1b, hr1, NP_PROT, 1);

    agg_mean_kernel<<<NP_PEP, 128, 0, sB>>>(hr0, rp_q, adj_q, mp, NP_PEP);
    gemm_bf16x3_kernel<<<gb_pep, 256, 0, sB>>>(
        mp, Wl1r, H, hp0, Wr1r, H, b1r, hp1, NP_PEP, 1);

    cudaEventRecord(evA1, sA);
    cudaEventRecord(evB1, sB);
    cudaStreamWaitEvent(s0, evA1, 0);
    cudaStreamWaitEvent(s0, evB1, 0);

    // ==== PHASE 2: SAGE layer 2 — prot chain (sA) ∥ pep chain (sB) ====
    cudaEventRecord(evF2, s0);
    cudaStreamWaitEvent(sA, evF2, 0);
    cudaStreamWaitEvent(sB, evF2, 0);

    agg_mean_kernel<<<NP_PROT, 128, 0, sA>>>(hp1, rp_p, adj_p, mr, NP_PROT);
    gemm_bf16x3_kernel<<<gb_prot, 256, 0, sA>>>(
        mr, Wl2b, H, hr1, Wr2b, H, b2b, hr0, NP_PROT, 0);

    agg_mean_kernel<<<NP_PEP, 128, 0, sB>>>(hr1, rp_q, adj_q, mp, NP_PEP);
    gemm_bf16x3_kernel<<<gb_pep, 256, 0, sB>>>(
        mp, Wl2r, H, hp1, Wr2r, H, b2r, hp0, NP_PEP, 0);

    cudaEventRecord(evA2, sA);
    cudaEventRecord(evB2, sB);
    cudaStreamWaitEvent(s0, evA2, 0);
    cudaStreamWaitEvent(s0, evB2, 0);

    // ==== classifier ====
    classifier_kernel<<<1024, 256, 0, s0>>>(hp0, hr0, el_src, el_dst, out, NEL);
}

// round 10
// speedup vs baseline: 1.4562x; 1.0025x over previous
#include <cuda_runtime.h>
#include <cuda_bf16.h>
#include <cstdint>

#define NP_PEP  50000
#define NP_PROT 8000
#define NE      1600000
#define NEL     200000
#define FIN     1280
#define H       128

// ---------------- scratch (static device globals; no runtime allocation) ----
__device__ float g_hp0[NP_PEP * H];
__device__ float g_hp1[NP_PEP * H];
__device__ float g_mp [NP_PEP * H];
__device__ float g_hr0[NP_PROT * H];
__device__ float g_hr1[NP_PROT * H];
__device__ float g_mr [NP_PROT * H];

__device__ int g_cnt_prot[NP_PROT];
__device__ int g_cnt_pep [NP_PEP];
__device__ int g_rp_prot [NP_PROT + 1];
__device__ int g_rp_pep  [NP_PEP + 1];
__device__ int g_cur_prot[NP_PROT];
__device__ int g_cur_pep [NP_PEP];
__device__ int g_part_prot[64];
__device__ int g_part_pep [64];
__device__ int g_adj_prot[NE];   // src pep ids grouped by prot dst
__device__ int g_adj_pep [NE];   // dst prot ids grouped by pep src

// ---------------- small helper kernels --------------------------------------
__global__ void zero2_kernel(int* a, int na, int* b, int nb) {
    int stride = gridDim.x * blockDim.x;
    for (int i = blockIdx.x * blockDim.x + threadIdx.x; i < na; i += stride) a[i] = 0;
    for (int i = blockIdx.x * blockDim.x + threadIdx.x; i < nb; i += stride) b[i] = 0;
}

__global__ void hist_kernel(const int* __restrict__ e_src, const int* __restrict__ e_dst,
                            int* __restrict__ cnt_prot, int* __restrict__ cnt_pep, int n) {
    int stride = gridDim.x * blockDim.x;
    for (int i = blockIdx.x * blockDim.x + threadIdx.x; i < n; i += stride) {
        atomicAdd(&cnt_prot[e_dst[i]], 1);
        atomicAdd(&cnt_pep [e_src[i]], 1);
    }
}

// ---------------- hierarchical scan: reduce / scan-partials / write ---------
#define SNB 64
#define SNT 256

__global__ void scan_reduce_kernel(const int* __restrict__ cnt, int* __restrict__ part, int n) {
    __shared__ int sh[SNT];
    int b = blockIdx.x, t = threadIdx.x;
    int chunk = (n + SNB - 1) / SNB;
    int s = b * chunk;
    int e = s + chunk; if (e > n) e = n;
    int loc = 0;
    for (int i = s + t; i < e; i += SNT) loc += cnt[i];
    sh[t] = loc;
    __syncthreads();
    for (int off = SNT / 2; off; off >>= 1) {
        if (t < off) sh[t] += sh[t + off];
        __syncthreads();
    }
    if (t == 0) part[b] = sh[0];
}

__global__ void scan_partial_kernel(int* __restrict__ part, int* __restrict__ rp, int n) {
    __shared__ int sh[SNB];
    int t = threadIdx.x;
    int v = part[t];
    sh[t] = v;
    __syncthreads();
    for (int off = 1; off < SNB; off <<= 1) {
        int u = (t >= off) ? sh[t - off] : 0;
        __syncthreads();
        sh[t] += u;
        __syncthreads();
    }
    part[t] = sh[t] - v;           // exclusive prefix of block partials
    if (t == SNB - 1) rp[n] = sh[t];
}

__global__ void scan_write_kernel(const int* __restrict__ cnt, const int* __restrict__ part,
                                  int* __restrict__ rp, int* __restrict__ cur, int n) {
    __shared__ int sh[SNT];
    __shared__ int base;
    int b = blockIdx.x, t = threadIdx.x;
    int chunk = (n + SNB - 1) / SNB;
    int s = b * chunk;
    int e = s + chunk; if (e > n) e = n;
    if (t == 0) base = part[b];
    int per = (chunk + SNT - 1) / SNT;
    int ts = s + t * per;
    int te = ts + per; if (te > e) te = e; if (ts > e) ts = e;
    int loc = 0;
    for (int i = ts; i < te; ++i) loc += cnt[i];
    sh[t] = loc;
    __syncthreads();
    int v = loc;
    for (int off = 1; off < SNT; off <<= 1) {
        int u = (t >= off) ? sh[t - off] : 0;
        __syncthreads();
        sh[t] += u;
        __syncthreads();
    }
    int run = base + sh[t] - v;    // exclusive prefix for this thread's range
    for (int i = ts; i < te; ++i) {
        rp[i] = run; cur[i] = run;
        run += cnt[i];
    }
}

__global__ void scatter_kernel(const int* __restrict__ e_src, const int* __restrict__ e_dst,
                               int* __restrict__ cur_prot, int* __restrict__ cur_pep,
                               int* __restrict__ adj_prot, int* __restrict__ adj_pep, int n) {
    int stride = gridDim.x * blockDim.x;
    for (int i = blockIdx.x * blockDim.x + threadIdx.x; i < n; i += stride) {
        int s = e_src[i], d = e_dst[i];
        int p = atomicAdd(&cur_prot[d], 1);
        adj_prot[p] = s;
        int q = atomicAdd(&cur_pep[s], 1);
        adj_pep[q] = d;
    }
}

// ---------------- CSR mean aggregation: one block per destination node ------
__global__ void __launch_bounds__(128) agg_mean_kernel(
    const float* __restrict__ hsrc, const int* __restrict__ rp,
    const int* __restrict__ adj, float* __restrict__ m, int n_dst) {
    int d = blockIdx.x;
    if (d >= n_dst) return;
    int s0 = rp[d], s1 = rp[d + 1];
    int lane = threadIdx.x & 31;
    int w    = threadIdx.x >> 5;

    float4 acc = make_float4(0.f, 0.f, 0.f, 0.f);
    for (int e = s0 + w; e < s1; e += 4) {
        int src = __ldg(&adj[e]);
        float4 v = ((const float4*)(hsrc + (size_t)src * H))[lane];
        acc.x += v.x; acc.y += v.y; acc.z += v.z; acc.w += v.w;
    }
    __shared__ float4 red[4][32];
    red[w][lane] = acc;
    __syncthreads();
    if (w == 0) {
        float4 a = red[0][lane], b = red[1][lane], c = red[2][lane], dd = red[3][lane];
        float deg = (float)(s1 - s0);
        float inv = deg > 0.f ? 1.f / deg : 0.f;
        float4 o;
        o.x = (a.x + b.x + c.x + dd.x) * inv;
        o.y = (a.y + b.y + c.y + dd.y) * inv;
        o.z = (a.z + b.z + c.z + dd.z) * inv;
        o.w = (a.w + b.w + c.w + dd.w) * inv;
        ((float4*)(m + (size_t)d * H))[lane] = o;
    }
}

// ---------------- bf16-split (3x) tensor-core GEMM --------------------------
// C[M,128] = relu?(A1@W1 + A2@W2 + bias), fp32 in/out, mma.sync bf16 inside.
// BM=128, BN=128(=H), BK=32, 256 threads = 8 warps (2x4 warp grid, 64x32 each)
#define GBM 128
#define GBK 32
#define SLD 40    // smem row stride in bf16 elems (80B = 5x16B -> ldmatrix conflict-free)

__device__ __forceinline__ void mma_bf16(float* c,
    uint32_t a0, uint32_t a1, uint32_t a2, uint32_t a3, uint32_t b0, uint32_t b1) {
    asm volatile(
        "mma.sync.aligned.m16n8k16.row.col.f32.bf16.bf16.f32 "
        "{%0,%1,%2,%3}, {%4,%5,%6,%7}, {%8,%9}, {%0,%1,%2,%3};"
        : "+f"(c[0]), "+f"(c[1]), "+f"(c[2]), "+f"(c[3])
        : "r"(a0), "r"(a1), "r"(a2), "r"(a3), "r"(b0), "r"(b1));
}

__device__ __forceinline__ void ldsm4(uint32_t* r, uint32_t addr) {
    asm volatile("ldmatrix.sync.aligned.m8n8.x4.shared.b16 {%0,%1,%2,%3}, [%4];"
        : "=r"(r[0]), "=r"(r[1]), "=r"(r[2]), "=r"(r[3]) : "r"(addr));
}

__global__ void __launch_bounds__(256) gemm_bf16x3_kernel(
    const float* __restrict__ A1, const float* __restrict__ W1, int K1,
    const float* __restrict__ A2, const float* __restrict__ W2, int K2,
    const float* __restrict__ bias, float* __restrict__ C, int M, int do_relu) {

    __shared__ __align__(16) __nv_bfloat16 As_hi[GBM * SLD];
    __shared__ __align__(16) __nv_bfloat16 As_lo[GBM * SLD];
    __shared__ __align__(16) __nv_bfloat16 Bs_hi[H * SLD];
    __shared__ __align__(16) __nv_bfloat16 Bs_lo[H * SLD];

    int tid  = threadIdx.x;
    int lane = tid & 31, wid = tid >> 5;
    int wm = wid & 1;        // 0..1 : 64-row half
    int wn = wid >> 1;       // 0..3 : 32-col group
    int m0 = blockIdx.x * GBM;

    float c[4][4][4];
#pragma unroll
    for (int i = 0; i < 4; ++i)
#pragma unroll
        for (int j = 0; j < 4; ++j)
#pragma unroll
            for (int k = 0; k < 4; ++k) c[i][j][k] = 0.f;

    int s1 = K1 / GBK;
    int s2 = (A2 != nullptr) ? (K2 / GBK) : 0;
    int ns = s1 + s2;

    // global->reg prefetch state
    float4 rA[4], rB[4];
    int arow = tid >> 1;                 // 0..127
    int kq   = (tid & 1) * 16;           // 0 or 16
    bool avalid = (m0 + arow) < M;

    auto LOAD = [&](int s) {
        const float* A; const float* W; int K; int kb;
        if (s < s1) { A = A1; W = W1; K = K1; kb = s; }
        else        { A = A2; W = W2; K = K2; kb = s - s1; }
        const float* ap = A + (size_t)(m0 + arow) * K + kb * GBK + kq;
#pragma unroll
        for (int j = 0; j < 4; ++j)
            rA[j] = avalid ? *(const float4*)(ap + j * 4) : make_float4(0.f, 0.f, 0.f, 0.f);
#pragma unroll
        for (int l = 0; l < 4; ++l) {
            int f = tid + l * 256;
            int kr = f >> 5, c4 = (f & 31) * 4;
            rB[l] = *(const float4*)(W + (size_t)(kb * GBK + kr) * H + c4);
        }
    };

    auto STORE = [&]() {
#pragma unroll
        for (int j = 0; j < 4; ++j) {
            float x[4] = { rA[j].x, rA[j].y, rA[j].z, rA[j].w };
            __nv_bfloat16 h[4], l[4];
#pragma unroll
            for (int q = 0; q < 4; ++q) {
                h[q] = __float2bfloat16(x[q]);
                l[q] = __float2bfloat16(x[q] - __bfloat162float(h[q]));
            }
            int base = arow * SLD + kq + j * 4;
            __nv_bfloat162 p;
            p.x = h[0]; p.y = h[1]; *(__nv_bfloat162*)&As_hi[base]     = p;
            p.x = h[2]; p.y = h[3]; *(__nv_bfloat162*)&As_hi[base + 2] = p;
            p.x = l[0]; p.y = l[1]; *(__nv_bfloat162*)&As_lo[base]     = p;
            p.x = l[2]; p.y = l[3]; *(__nv_bfloat162*)&As_lo[base + 2] = p;
        }
#pragma unroll
        for (int ll = 0; ll < 4; ++ll) {
            int f = tid + ll * 256;
            int kr = f >> 5, c4 = (f & 31) * 4;
            float x[4] = { rB[ll].x, rB[ll].y, rB[ll].z, rB[ll].w };
#pragma unroll
            for (int j = 0; j < 4; ++j) {
                __nv_bfloat16 hh = __float2bfloat16(x[j]);
                Bs_hi[(c4 + j) * SLD + kr] = hh;
                Bs_lo[(c4 + j) * SLD + kr] = __float2bfloat16(x[j] - __bfloat162float(hh));
            }
        }
    };

    // per-lane ldmatrix row/col offsets
    int a_r = (lane & 7) + ((lane >> 3) & 1) * 8;
    int a_c = (lane >> 4) * 8;
    int b_r = (lane & 7) + ((lane >> 4) & 1) * 8;
    int b_c = ((lane >> 3) & 1) * 8;
    uint32_t as_hi = (uint32_t)__cvta_generic_to_shared(As_hi);
    uint32_t as_lo = (uint32_t)__cvta_generic_to_shared(As_lo);
    uint32_t bs_hi = (uint32_t)__cvta_generic_to_shared(Bs_hi);
    uint32_t bs_lo = (uint32_t)__cvta_generic_to_shared(Bs_lo);

    auto COMPUTE = [&]() {
#pragma unroll
        for (int kk = 0; kk < GBK; kk += 16) {
            uint32_t ah[4][4], al[4][4], bh[2][4], bl[2][4];
#pragma unroll
            for (int mt = 0; mt < 4; ++mt) {
                uint32_t off = (uint32_t)(((wm * 64 + mt * 16 + a_r) * SLD + kk + a_c) * 2);
                ldsm4(ah[mt], as_hi + off);
                ldsm4(al[mt], as_lo + off);
            }
#pragma unroll
            for (int p = 0; p < 2; ++p) {
                uint32_t off = (uint32_t)(((wn * 32 + p * 16 + b_r) * SLD + kk + b_c) * 2);
                ldsm4(bh[p], bs_hi + off);
                ldsm4(bl[p], bs_lo + off);
            }
#pragma unroll
            for (int mt = 0; mt < 4; ++mt)
#pragma unroll
                for (int nt = 0; nt < 4; ++nt) {
                    uint32_t h0 = bh[nt >> 1][(nt & 1) * 2], h1 = bh[nt >> 1][(nt & 1) * 2 + 1];
                    uint32_t l0 = bl[nt >> 1][(nt & 1) * 2], l1 = bl[nt >> 1][(nt & 1) * 2 + 1];
                    mma_bf16(c[mt][nt], ah[mt][0], ah[mt][1], ah[mt][2], ah[mt][3], h0, h1);
                    mma_bf16(c[mt][nt], ah[mt][0], ah[mt][1], ah[mt][2], ah[mt][3], l0, l1);
                    mma_bf16(c[mt][nt], al[mt][0], al[mt][1], al[mt][2], al[mt][3], h0, h1);
                }
        }
    };

    LOAD(0);
    for (int s = 0; s < ns; ++s) {
        __syncthreads();           // previous compute done before smem overwrite
        STORE();
        __syncthreads();
        if (s + 1 < ns) LOAD(s + 1);   // LDGs overlap with mma below
        COMPUTE();
    }

    // epilogue: bias (+relu) and fp32 store
    int g = lane >> 2, t = lane & 3;
#pragma unroll
    for (int mt = 0; mt < 4; ++mt) {
        int r0 = m0 + wm * 64 + mt * 16 + g;
#pragma unroll
        for (int nt = 0; nt < 4; ++nt) {
            int col = wn * 32 + nt * 8 + t * 2;
            float2 bv = *(const float2*)&bias[col];
            float o0 = c[mt][nt][0] + bv.x, o1 = c[mt][nt][1] + bv.y;
            float o2 = c[mt][nt][2] + bv.x, o3 = c[mt][nt][3] + bv.y;
            if (do_relu) {
                o0 = fmaxf(o0, 0.f); o1 = fmaxf(o1, 0.f);
                o2 = fmaxf(o2, 0.f); o3 = fmaxf(o3, 0.f);
            }
            if (r0 < M) { float2 v = make_float2(o0, o1); *(float2*)&C[(size_t)r0 * H + col] = v; }
            int r1 = r0 + 8;
            if (r1 < M) { float2 v = make_float2(o2, o3); *(float2*)&C[(size_t)r1 * H + col] = v; }
        }
    }
}

// ---------------- classifier: warp per edge, 128-dim dot --------------------
__global__ void classifier_kernel(const float* __restrict__ hp, const float* __restrict__ hr,
                                  const int* __restrict__ es, const int* __restrict__ ed,
                                  float* __restrict__ out, int n) {
    int gtid = blockIdx.x * blockDim.x + threadIdx.x;
    int wid  = gtid >> 5;
    int lane = threadIdx.x & 31;
    int nw   = (gridDim.x * blockDim.x) >> 5;
    for (int e = wid; e < n; e += nw) {
        int s = es[e], d = ed[e];
        float4 a = ((const float4*)(hp + (size_t)s * H))[lane];
        float4 b = ((const float4*)(hr + (size_t)d * H))[lane];
        float v = a.x * b.x + a.y * b.y + a.z * b.z + a.w * b.w;
#pragma unroll
        for (int o = 16; o; o >>= 1) v += __shfl_xor_sync(0xFFFFFFFFu, v, o);
        if (lane == 0) out[e] = v;
    }
}

// ---------------- launch ------------------------------------------------------
extern "C" void kernel_launch(void* const* d_in, const int* in_sizes, int n_in,
                              void* d_out, int out_size) {
    const float* x_pep  = (const float*)d_in[0];
    const float* x_prot = (const float*)d_in[1];
    const int*   e_src  = (const int*)d_in[2];
    const int*   e_dst  = (const int*)d_in[3];
    const int*   el_src = (const int*)d_in[4];
    const int*   el_dst = (const int*)d_in[5];

    bool ref_order = (in_sizes[12] == H);
    const float *W_pep  = (const float*)d_in[6];
    const float *b_pep  = (const float*)d_in[7];
    const float *W_prot = (const float*)d_in[8];
    const float *b_prot = (const float*)d_in[9];
    const float *Wl1b, *Wr1b, *b1b, *Wl1r, *Wr1r, *b1r;
    const float *Wl2b, *Wr2b, *b2b, *Wl2r, *Wr2r, *b2r;
    if (ref_order) {
        Wl1b = (const float*)d_in[10]; Wr1b = (const float*)d_in[11]; b1b = (const float*)d_in[12];
        Wl1r = (const float*)d_in[13]; Wr1r = (const float*)d_in[14]; b1r = (const float*)d_in[15];
        Wl2b = (const float*)d_in[16]; Wr2b = (const float*)d_in[17]; b2b = (const float*)d_in[18];
        Wl2r = (const float*)d_in[19]; Wr2r = (const float*)d_in[20]; b2r = (const float*)d_in[21];
    } else {
        Wl1b = (const float*)d_in[10]; Wr1b = (const float*)d_in[11];
        Wl1r = (const float*)d_in[12]; Wr1r = (const float*)d_in[13];
        Wl2b = (const float*)d_in[14]; Wr2b = (const float*)d_in[15];
        Wl2r = (const float*)d_in[16]; Wr2r = (const float*)d_in[17];
        b1b  = (const float*)d_in[18]; b1r  = (const float*)d_in[19];
        b2b  = (const float*)d_in[20]; b2r  = (const float*)d_in[21];
    }
    float* out = (float*)d_out;

    float *hp0, *hp1, *mp, *hr0, *hr1, *mr;
    int *cnt_p, *cnt_q, *rp_p, *rp_q, *cur_p, *cur_q, *adj_p, *adj_q, *part_p, *part_q;
    cudaGetSymbolAddress((void**)&hp0, g_hp0);
    cudaGetSymbolAddress((void**)&hp1, g_hp1);
    cudaGetSymbolAddress((void**)&mp,  g_mp);
    cudaGetSymbolAddress((void**)&hr0, g_hr0);
    cudaGetSymbolAddress((void**)&hr1, g_hr1);
    cudaGetSymbolAddress((void**)&mr,  g_mr);
    cudaGetSymbolAddress((void**)&cnt_p,  g_cnt_prot);
    cudaGetSymbolAddress((void**)&cnt_q,  g_cnt_pep);
    cudaGetSymbolAddress((void**)&rp_p,   g_rp_prot);
    cudaGetSymbolAddress((void**)&rp_q,   g_rp_pep);
    cudaGetSymbolAddress((void**)&cur_p,  g_cur_prot);
    cudaGetSymbolAddress((void**)&cur_q,  g_cur_pep);
    cudaGetSymbolAddress((void**)&adj_p,  g_adj_prot);
    cudaGetSymbolAddress((void**)&adj_q,  g_adj_pep);
    cudaGetSymbolAddress((void**)&part_p, g_part_prot);
    cudaGetSymbolAddress((void**)&part_q, g_part_pep);

    // ---- streams/events for graph-level concurrency (host objects only; ----
    // ---- created once, no device memory involved)                        ----
    static cudaStream_t sA = nullptr, sB = nullptr;
    static cudaEvent_t  evF0 = nullptr, evF1 = nullptr, evF2 = nullptr;
    static cudaEvent_t  evA0 = nullptr, evB0 = nullptr, evA1 = nullptr, evB1 = nullptr;
    static cudaEvent_t  evA2 = nullptr, evB2 = nullptr;
    if (sA == nullptr) {
        cudaStreamCreateWithFlags(&sA, cudaStreamNonBlocking);
        cudaStreamCreateWithFlags(&sB, cudaStreamNonBlocking);
        cudaEventCreateWithFlags(&evF0, cudaEventDisableTiming);
        cudaEventCreateWithFlags(&evF1, cudaEventDisableTiming);
        cudaEventCreateWithFlags(&evF2, cudaEventDisableTiming);
        cudaEventCreateWithFlags(&evA0, cudaEventDisableTiming);
        cudaEventCreateWithFlags(&evB0, cudaEventDisableTiming);
        cudaEventCreateWithFlags(&evA1, cudaEventDisableTiming);
        cudaEventCreateWithFlags(&evB1, cudaEventDisableTiming);
        cudaEventCreateWithFlags(&evA2, cudaEventDisableTiming);
        cudaEventCreateWithFlags(&evB2, cudaEventDisableTiming);
    }
    // s0 must be the stream the harness captures; <<<>>> maps to the default
    // stream, which previous rounds proved is the captured one.
    cudaStream_t s0 = cudaStreamPerThread;
    // If the legacy stream is the capturing one, fall back to it.
    {
        cudaStreamCaptureStatus st = cudaStreamCaptureStatusNone;
        cudaStreamIsCapturing(cudaStreamPerThread, &st);
        if (st != cudaStreamCaptureStatusActive) {
            cudaStreamCaptureStatus st2 = cudaStreamCaptureStatusNone;
            cudaStreamIsCapturing(cudaStreamLegacy, &st2);
            if (st2 == cudaStreamCaptureStatusActive) s0 = cudaStreamLegacy;
        }
    }

    int gb_pep  = (NP_PEP  + GBM - 1) / GBM;   // 391
    int gb_prot = (NP_PROT + GBM - 1) / GBM;   // 63

    // ==== PHASE 0: fork — CSR build (s0) ∥ pep proj (sA) ∥ prot proj (sB) ====
    cudaEventRecord(evF0, s0);
    cudaStreamWaitEvent(sA, evF0, 0);
    cudaStreamWaitEvent(sB, evF0, 0);

    gemm_bf16x3_kernel<<<gb_pep, 256, 0, sA>>>(
        x_pep, W_pep, FIN, nullptr, nullptr, 0, b_pep, hp0, NP_PEP, 0);
    gemm_bf16x3_kernel<<<gb_prot, 256, 0, sB>>>(
        x_prot, W_prot, FIN, nullptr, nullptr, 0, b_prot, hr0, NP_PROT, 0);

    zero2_kernel<<<256, 256, 0, s0>>>(cnt_p, NP_PROT, cnt_q, NP_PEP);
    hist_kernel<<<2048, 256, 0, s0>>>(e_src, e_dst, cnt_p, cnt_q, NE);
    scan_reduce_kernel<<<SNB, SNT, 0, s0>>>(cnt_p, part_p, NP_PROT);
    scan_reduce_kernel<<<SNB, SNT, 0, s0>>>(cnt_q, part_q, NP_PEP);
    scan_partial_kernel<<<1, SNB, 0, s0>>>(part_p, rp_p, NP_PROT);
    scan_partial_kernel<<<1, SNB, 0, s0>>>(part_q, rp_q, NP_PEP);
    scan_write_kernel<<<SNB, SNT, 0, s0>>>(cnt_p, part_p, rp_p, cur_p, NP_PROT);
    scan_write_kernel<<<SNB, SNT, 0, s0>>>(cnt_q, part_q, rp_q, cur_q, NP_PEP);
    scatter_kernel<<<2048, 256, 0, s0>>>(e_src, e_dst, cur_p, cur_q, adj_p, adj_q, NE);

    // join all three
    cudaEventRecord(evA0, sA);
    cudaEventRecord(evB0, sB);
    cudaStreamWaitEvent(s0, evA0, 0);
    cudaStreamWaitEvent(s0, evB0, 0);

    // ==== PHASE 1: SAGE layer 1 — prot chain (sA) ∥ pep chain (sB) ====
    cudaEventRecord(evF1, s0);
    cudaStreamWaitEvent(sA, evF1, 0);
    cudaStreamWaitEvent(sB, evF1, 0);

    agg_mean_kernel<<<NP_PROT, 128, 0, sA>>>(hp0, rp_p, adj_p, mr, NP_PROT);
    gemm_bf16x3_kernel<<<gb_prot, 256, 0, sA>>>(
        mr, Wl1b, H, hr0, Wr1b, H, b1b, hr1, NP_PROT, 1);

    agg_mean_kernel<<<NP_PEP, 128, 0, sB>>>(hr0, rp_q, adj_q, mp, NP_PEP);
    gemm_bf16x3_kernel<<<gb_pep, 256, 0, sB>>>(
        mp, Wl1r, H, hp0, Wr1r, H, b1r, hp1, NP_PEP, 1);

    cudaEventRecord(evA1, sA);
    cudaEventRecord(evB1, sB);
    cudaStreamWaitEvent(s0, evA1, 0);
    cudaStreamWaitEvent(s0, evB1, 0);

    // ==== PHASE 2: SAGE layer 2 — prot chain (sA) ∥ pep chain (sB) ====
    cudaEventRecord(evF2, s0);
    cudaStreamWaitEvent(sA, evF2, 0);
    cudaStreamWaitEvent(sB, evF2, 0);

    agg_mean_kernel<<<NP_PROT, 128, 0, sA>>>(hp1, rp_p, adj_p, mr, NP_PROT);
    gemm_bf16x3_kernel<<<gb_prot, 256, 0, sA>>>(
        mr, Wl2b, H, hr1, Wr2b, H, b2b, hr0, NP_PROT, 0);

    agg_mean_kernel<<<NP_PEP, 128, 0, sB>>>(hr1, rp_q, adj_q, mp, NP_PEP);
    gemm_bf16x3_kernel<<<gb_pep, 256, 0, sB>>>(
        mp, Wl2r, H, hp1, Wr2r, H, b2r, hp0, NP_PEP, 0);

    cudaEventRecord(evA2, sA);
    cudaEventRecord(evB2, sB);
    cudaStreamWaitEvent(s0, evA2, 0);
    cudaStreamWaitEvent(s0, evB2, 0);

    // ==== classifier ====
    classifier_kernel<<<1024, 256, 0, s0>>>(hp0, hr0, el_src, el_dst, out, NEL);
}